// round 17
// baseline (speedup 1.0000x reference)
#include <cuda_runtime.h>
#include <math.h>
#include <stdint.h>

#define HID 1024
#define NB  4096
#define FULL 0xFFFFFFFFu

// Fast softplus: MUFU-backed log/exp.
__device__ __forceinline__ float softplus_fast(float z) {
    return fmaxf(z, 0.0f) + __logf(1.0f + __expf(-fabsf(z)));
}
__device__ __forceinline__ float kl_term_f(float mu, float sigma, float inv_ps) {
    float r = sigma * inv_ps;
    float m = mu * inv_ps;
    return 0.5f * (fmaf(r, r, -1.0f) + m * m - 2.0f * __logf(r));
}

// Packed f32x2 helpers (sm_103a). Per-channel sequence bit-exact vs scalar.
__device__ __forceinline__ unsigned long long f2pack(float lo, float hi) {
    unsigned long long r;
    asm("mov.b64 %0, {%1, %2};" : "=l"(r) : "f"(lo), "f"(hi));
    return r;
}
__device__ __forceinline__ void f2unpack(unsigned long long v, float& lo, float& hi) {
    asm("mov.b64 {%0, %1}, %2;" : "=f"(lo), "=f"(hi) : "l"(v));
}
__device__ __forceinline__ unsigned long long f2add(unsigned long long a, unsigned long long b) {
    unsigned long long r;
    asm("add.rn.f32x2 %0, %1, %2;" : "=l"(r) : "l"(a), "l"(b));
    return r;
}

// Piecewise-monotone bucketizer, bit-identical between build and query.
__device__ __forceinline__ int qidx_ext(float v) {
    if (v >= 71.5f)  return 3967;                                     // incl +INF
    if (v >= 7.5f)   return 3904 + __float2int_rd(v - 7.5f);          // [3904,3968)
    if (v >= -7.5f)  return 64 + __float2int_rd((v + 7.5f) * 256.0f); // [64,3904)
    if (v >= -71.5f) return __float2int_rd(v + 71.5f);                // [0,64)
    return 0;                                                          // incl -INF
}

// Shared layout (~45.5 KB static).
struct Smem {
    float4   C[HID + 1];          // delta scratch, then final coefficients
    union R2 {
        int cnt[NB];              // histogram
        unsigned long long k[HID];// packed (order-key(t), idx)
    } r2;
    uint16_t B[NB];               // bucket -> exclusive start (seed table)
    float    t[HID + 1];          // sorted breakpoints + INF sentinel
    float    ws[4][32];           // per-warp delta-scan totals
    float    bw[4][32];           // per-warp baseline partials
    float    kw[32];              // per-warp KL partials (block 0)
    int      swi[32];
    float    b2v[2];
};

__global__ void __launch_bounds__(1024, 1) fused_kernel(
    const float* __restrict__ x,
    const float* __restrict__ W1_mu, const float* __restrict__ W1_rho,
    const float* __restrict__ b1_mu, const float* __restrict__ b1_rho,
    const float* __restrict__ W2_mu, const float* __restrict__ W2_rho,
    const float* __restrict__ b2_mu, const float* __restrict__ b2_rho,
    const float* __restrict__ eps_W1, const float* __restrict__ eps_b1,
    const float* __restrict__ eps_W2, const float* __restrict__ eps_b2,
    float* __restrict__ out, int N)
{
    __shared__ Smem S;
    const int j    = threadIdx.x;
    const int lane = j & 31;
    const int warp = j >> 5;
    const bool doKL = (blockIdx.x == 0);

    // Zero histogram early, vectorized (ordered by barrier #1).
    ((int4*)S.r2.cnt)[j] = make_int4(0, 0, 0, 0);

    // Prefetch this thread's eval input.
    const int  i  = blockIdx.x * 1024 + j;
    const bool ok = (i < N);
    const float xv = ok ? __ldg(x + i) : 0.0f;

    // ---- Phase A: perturbed params, breakpoint, deltas, baseline, KL ----
    const float sW1 = softplus_fast(W1_rho[j]);
    const float w   = W1_mu[j] + sW1 * eps_W1[j];
    const float sb1 = softplus_fast(b1_rho[j]);
    const float b   = b1_mu[j] + sb1 * eps_b1[j];
    const float sc0 = softplus_fast(W2_rho[j]);
    const float c0  = W2_mu[j] + sc0 * eps_W2[j];
    const float sc1 = softplus_fast(W2_rho[HID + j]);
    const float c1  = W2_mu[HID + j] + sc1 * eps_W2[HID + j];

    float t, dA0, dB0, dA1, dB1;
    float bA0 = 0.0f, bB0 = 0.0f, bA1 = 0.0f, bB1 = 0.0f;
    if (w > 0.0f) {
        t = __fdividef(-b, w);
        dA0 = c0 * w;  dB0 = c0 * b;  dA1 = c1 * w;  dB1 = c1 * b;
    } else if (w < 0.0f) {
        t = __fdividef(-b, w);
        dA0 = -(c0 * w); dB0 = -(c0 * b); dA1 = -(c1 * w); dB1 = -(c1 * b);
        bA0 = c0 * w; bB0 = c0 * b; bA1 = c1 * w; bB1 = c1 * b;
    } else {
        t = INFINITY;
        dA0 = dB0 = dA1 = dB1 = 0.0f;
        if (b > 0.0f) { bB0 = c0 * b; bB1 = c1 * b; }
    }

    // Perturbed b2, once per block.
    if (warp == 9 && lane < 2)
        S.b2v[lane] = b2_mu[lane] + softplus_fast(b2_rho[lane]) * eps_b2[lane];

    // Baseline warp reductions, packed f32x2.
    {
        unsigned long long p01 = f2pack(bA0, bB0);
        unsigned long long p23 = f2pack(bA1, bB1);
        #pragma unroll
        for (int o = 16; o > 0; o >>= 1) {
            p01 = f2add(p01, __shfl_xor_sync(FULL, p01, o));
            p23 = f2add(p23, __shfl_xor_sync(FULL, p23, o));
        }
        if (lane == 0) {
            float a0, a1, a2, a3;
            f2unpack(p01, a0, a1); f2unpack(p23, a2, a3);
            S.bw[0][warp] = a0; S.bw[1][warp] = a1;
            S.bw[2][warp] = a2; S.bw[3][warp] = a3;
        }
    }

    // KL partials: block 0 only.
    if (doKL) {
        const float INV_PS1 = 0.25f;
        const float INV_PS2 = 32.0f / 2.25f;
        float kl = kl_term_f(W1_mu[j],       sW1, INV_PS1)
                 + kl_term_f(b1_mu[j],       sb1, INV_PS1)
                 + kl_term_f(W2_mu[j],       sc0, INV_PS2)
                 + kl_term_f(W2_mu[HID + j], sc1, INV_PS2);
        if (j < 2) kl += kl_term_f(b2_mu[j], softplus_fast(b2_rho[j]), INV_PS2);
        #pragma unroll
        for (int o = 16; o > 0; o >>= 1) kl += __shfl_xor_sync(FULL, kl, o);
        if (lane == 0) S.kw[warp] = kl;
    }

    const int cl = qidx_ext(t);

    __syncthreads();                               // #1: cnt zeroed, bw/kw visible

    // Histogram atomic (sort) — and, in its latency shadow, the baseline
    // totals (every warp redundantly) + the KL final reduce (block 0, warp 8).
    const int o_in_bucket = atomicAdd(&S.r2.cnt[cl], 1);

    float tot0, tot1, tot2, tot3;
    {
        float q0 = S.bw[0][lane], q1 = S.bw[1][lane];
        float q2 = S.bw[2][lane], q3 = S.bw[3][lane];
        #pragma unroll
        for (int o = 16; o > 0; o >>= 1) {
            q0 += __shfl_xor_sync(FULL, q0, o);
            q1 += __shfl_xor_sync(FULL, q1, o);
            q2 += __shfl_xor_sync(FULL, q2, o);
            q3 += __shfl_xor_sync(FULL, q3, o);
        }
        tot0 = __shfl_sync(FULL, q0, 0);
        tot1 = __shfl_sync(FULL, q1, 0);
        tot2 = __shfl_sync(FULL, q2, 0);
        tot3 = __shfl_sync(FULL, q3, 0);
    }
    if (doKL && warp == 8) {
        float v = S.kw[lane];
        #pragma unroll
        for (int o = 16; o > 0; o >>= 1) v += __shfl_xor_sync(FULL, v, o);
        if (lane == 0) out[2 * (size_t)N] = v;     // KL
    }

    __syncthreads();                               // #2: histogram done

    // Exclusive scan of histogram -> B (cross-warp prefix redundant per warp).
    {
        int4 c4 = ((const int4*)S.r2.cnt)[j];
        int tsum = c4.x + c4.y + c4.z + c4.w;
        int incl = tsum;
        #pragma unroll
        for (int o = 1; o < 32; o <<= 1) {
            int u = __shfl_up_sync(FULL, incl, o);
            if (lane >= o) incl += u;
        }
        if (lane == 31) S.swi[warp] = incl;
        __syncthreads();                           // #3: swi + all c4 reads done
        int sv = S.swi[lane];
        #pragma unroll
        for (int o = 1; o < 32; o <<= 1) {
            int u = __shfl_up_sync(FULL, sv, o);
            if (lane >= o) sv += u;
        }
        const int wpre = (warp == 0) ? 0 : __shfl_sync(FULL, sv, warp - 1);
        int base = wpre + (incl - tsum);
        ushort4 o4;
        o4.x = (uint16_t)base;
        o4.y = (uint16_t)(base + c4.x);
        o4.z = (uint16_t)(base + c4.x + c4.y);
        o4.w = (uint16_t)(base + c4.x + c4.y + c4.z);
        ((ushort4*)S.B)[j] = o4;
    }
    __syncthreads();                               // #4: B complete; cnt reusable

    // Eval seed (B final from here).
    const int m_seed = (int)S.B[qidx_ext(xv)];

    // Packed order key: monotone uint map of t, tie-broken by original index.
    unsigned long long pk;
    {
        uint32_t u = __float_as_uint(t);
        uint32_t k32 = u ^ ((u & 0x80000000u) ? 0xFFFFFFFFu : 0x80000000u);
        pk = ((unsigned long long)k32 << 10) | (unsigned)j;
    }

    // Preliminary key scatter.
    const int bstart = (int)S.B[cl];
    S.r2.k[bstart + o_in_bucket] = pk;
    __syncthreads();                               // #5

    // Exact deterministic rank within bucket.
    int f;
    {
        const int bend = (int)S.B[cl + 1];
        int r = 0;
        for (int k = bstart; k < bend; k++)
            r += (S.r2.k[k] < pk);
        f = bstart + r;
    }
    // Deterministic scatter straight from registers (disjoint arrays).
    S.t[f] = t;
    S.C[f] = make_float4(dA0, dB0, dA1, dB1);
    if (j == 0) S.t[HID] = INFINITY;
    __syncthreads();                               // #6

    // Own sorted slot's deltas (one LDS.128).
    float v0, v1, v2, v3;
    {
        float4 dv = S.C[j];
        v0 = dv.x; v1 = dv.y; v2 = dv.z; v3 = dv.w;
    }

    // 4-channel inclusive warp scan, packed f32x2.
    {
        unsigned long long s01 = f2pack(v0, v1);
        unsigned long long s23 = f2pack(v2, v3);
        #pragma unroll
        for (int o = 1; o < 32; o <<= 1) {
            unsigned long long u01 = __shfl_up_sync(FULL, s01, o);
            unsigned long long u23 = __shfl_up_sync(FULL, s23, o);
            if (lane >= o) { s01 = f2add(s01, u01); s23 = f2add(s23, u23); }
        }
        f2unpack(s01, v0, v1); f2unpack(s23, v2, v3);
    }
    if (lane == 31) {
        S.ws[0][warp] = v0; S.ws[1][warp] = v1;
        S.ws[2][warp] = v2; S.ws[3][warp] = v3;
    }
    __syncthreads();                               // #7: C[j] reads + ws done

    // Cross-warp delta prefixes: redundant per-warp scans (no extra barrier).
    float woff0, woff1, woff2, woff3;
    {
        float s0 = S.ws[0][lane], s1 = S.ws[1][lane];
        float s2 = S.ws[2][lane], s3 = S.ws[3][lane];
        #pragma unroll
        for (int o = 1; o < 32; o <<= 1) {
            float u0 = __shfl_up_sync(FULL, s0, o);
            float u1 = __shfl_up_sync(FULL, s1, o);
            float u2 = __shfl_up_sync(FULL, s2, o);
            float u3 = __shfl_up_sync(FULL, s3, o);
            if (lane >= o) { s0 += u0; s1 += u1; s2 += u2; s3 += u3; }
        }
        const int src = (warp == 0) ? 0 : (warp - 1);
        woff0 = (warp == 0) ? 0.0f : __shfl_sync(FULL, s0, src);
        woff1 = (warp == 0) ? 0.0f : __shfl_sync(FULL, s1, src);
        woff2 = (warp == 0) ? 0.0f : __shfl_sync(FULL, s2, src);
        woff3 = (warp == 0) ? 0.0f : __shfl_sync(FULL, s3, src);
    }

    const float base0 = tot0;
    const float base1 = tot1 + S.b2v[0];
    const float base2 = tot2;
    const float base3 = tot3 + S.b2v[1];

    float4 c;
    c.x = base0 + woff0 + v0;
    c.y = base1 + woff1 + v1;
    c.z = base2 + woff2 + v2;
    c.w = base3 + woff3 + v3;
    S.C[j + 1] = c;
    if (j == 0) S.C[0] = make_float4(base0, base1, base2, base3);
    __syncthreads();                               // #8: tables complete

    // ---- Eval: bucket-seeded lower-bound + short LDS walk ----
    if (ok) {
        int m = m_seed;
        while (S.t[m] <= xv) ++m;      // sentinel bounds the walk

        float4 cc = S.C[m];
        out[i] = fmaf(cc.x, xv, cc.y);
        float h = fmaf(cc.z, xv, cc.w);
        out[N + i] = 1e-5f + softplus_fast(h);
    }
}

extern "C" void kernel_launch(void* const* d_in, const int* in_sizes, int n_in,
                              void* d_out, int out_size) {
    const float* x      = (const float*)d_in[0];
    const float* W1_mu  = (const float*)d_in[1];
    const float* W1_rho = (const float*)d_in[2];
    const float* b1_mu  = (const float*)d_in[3];
    const float* b1_rho = (const float*)d_in[4];
    const float* W2_mu  = (const float*)d_in[5];
    const float* W2_rho = (const float*)d_in[6];
    const float* b2_mu  = (const float*)d_in[7];
    const float* b2_rho = (const float*)d_in[8];
    const float* eps_W1 = (const float*)d_in[9];
    const float* eps_b1 = (const float*)d_in[10];
    const float* eps_W2 = (const float*)d_in[11];
    const float* eps_b2 = (const float*)d_in[12];

    float* out = (float*)d_out;
    const int N = in_sizes[0];

    int blocks = (N + 1023) / 1024;   // 128 for N=131072
    fused_kernel<<<blocks, 1024>>>(x,
        W1_mu, W1_rho, b1_mu, b1_rho, W2_mu, W2_rho, b2_mu, b2_rho,
        eps_W1, eps_b1, eps_W2, eps_b2, out, N);
}